// round 2
// baseline (speedup 1.0000x reference)
#include <cuda_runtime.h>
#include <cstdint>

// Problem constants (fixed by the reference)
#define CIN   64
#define COUT  64
#define KOFF  27
#define MPAIR 131072
#define NOUT  262144
#define EPS   1e-5f
#define SLOPE 0.01f

// BN statistics scratch
__device__ float g_sum[COUT];
__device__ float g_sumsq[COUT];

// ---------------------------------------------------------------------------
// Kernel 0: zero output accumulator + stats scratch
// ---------------------------------------------------------------------------
__global__ void zero_kernel(float4* __restrict__ out4) {
    int idx = blockIdx.x * blockDim.x + threadIdx.x;   // 4,194,304 float4s
    out4[idx] = make_float4(0.f, 0.f, 0.f, 0.f);
    if (blockIdx.x == 0 && threadIdx.x < COUT) {
        g_sum[threadIdx.x]   = 0.f;
        g_sumsq[threadIdx.x] = 0.f;
    }
}

// ---------------------------------------------------------------------------
// Kernel 1: sparse conv, gather -> tf32 mma.sync -> red.v4 scatter
// Block: 256 threads (8 warps). Each warp handles 16 pairs per tile,
// block handles 128 pairs per tile, 4 tiles per block (W smem amortized).
// grid = (M / 512, K)
// ---------------------------------------------------------------------------
__global__ void __launch_bounds__(256)
conv_kernel(const float* __restrict__ feats,
            const float* __restrict__ W,
            const int*   __restrict__ in_map,
            const int*   __restrict__ out_map,
            float*       __restrict__ out)
{
    // W tile in smem as tf32 bits, padded leading dim 72 (72 % 32 == 8 ->
    // B-frag LDS addresses (72*a + r) are bank-bijective, conflict-free)
    __shared__ uint32_t Ws[CIN * 72];

    const int k   = blockIdx.y;
    const int tid = threadIdx.x;

    const float* Wk = W + k * (CIN * COUT);
    for (int i = tid; i < CIN * COUT; i += 256) {
        int kk = i >> 6, n = i & 63;
        uint32_t t;
        asm("cvt.rna.tf32.f32 %0, %1;" : "=r"(t) : "f"(Wk[i]));
        Ws[kk * 72 + n] = t;
    }
    __syncthreads();

    const int warp = tid >> 5;
    const int lane = tid & 31;
    const int r = lane >> 2;   // 0..7  (row within mma group)
    const int a = lane & 3;    // 0..3  (thread-in-group)

    const int* im = in_map  + k * MPAIR;
    const int* om = out_map + k * MPAIR;

    #pragma unroll 1
    for (int t = 0; t < 4; t++) {
        const int base = (blockIdx.x * 4 + t) * 128 + warp * 16;
        const int p0 = base + r;
        const int p1 = p0 + 8;

        const float* arow0 = feats + (size_t)im[p0] * CIN;
        const float* arow1 = feats + (size_t)im[p1] * CIN;

        float acc[8][4];
        #pragma unroll
        for (int j = 0; j < 8; j++)
            #pragma unroll
            for (int q = 0; q < 4; q++) acc[j][q] = 0.f;

        #pragma unroll
        for (int kk = 0; kk < 8; kk++) {
            const int c0 = kk * 8 + a;
            uint32_t a0, a1, a2, a3;
            asm("cvt.rna.tf32.f32 %0, %1;" : "=r"(a0) : "f"(arow0[c0]));
            asm("cvt.rna.tf32.f32 %0, %1;" : "=r"(a1) : "f"(arow1[c0]));
            asm("cvt.rna.tf32.f32 %0, %1;" : "=r"(a2) : "f"(arow0[c0 + 4]));
            asm("cvt.rna.tf32.f32 %0, %1;" : "=r"(a3) : "f"(arow1[c0 + 4]));

            #pragma unroll
            for (int j = 0; j < 8; j++) {
                const uint32_t b0 = Ws[(kk * 8 + a)     * 72 + j * 8 + r];
                const uint32_t b1 = Ws[(kk * 8 + a + 4) * 72 + j * 8 + r];
                asm volatile(
                    "mma.sync.aligned.m16n8k8.row.col.f32.tf32.tf32.f32 "
                    "{%0,%1,%2,%3}, {%4,%5,%6,%7}, {%8,%9}, {%0,%1,%2,%3};"
                    : "+f"(acc[j][0]), "+f"(acc[j][1]),
                      "+f"(acc[j][2]), "+f"(acc[j][3])
                    : "r"(a0), "r"(a1), "r"(a2), "r"(a3),
                      "r"(b0), "r"(b1));
            }
        }

        // Epilogue: pair-exchange (lane^1) so each issuing thread owns a
        // 4-contiguous column quad -> red.global.add.v4.f32 (16B aligned).
        float* orow0 = out + (size_t)om[p0] * COUT;
        float* orow1 = out + (size_t)om[p1] * COUT;

        #pragma unroll
        for (int j = 0; j < 8; j++) {
            const float pc0 = __shfl_xor_sync(0xffffffffu, acc[j][0], 1);
            const float pc1 = __shfl_xor_sync(0xffffffffu, acc[j][1], 1);
            const float pc2 = __shfl_xor_sync(0xffffffffu, acc[j][2], 1);
            const float pc3 = __shfl_xor_sync(0xffffffffu, acc[j][3], 1);
            if ((j & 1) == (a & 1)) {
                const int nb = j * 8 + 4 * (a >> 1);
                float v0, v1, v2, v3, w0, w1, w2, w3;
                if ((a & 1) == 0) {
                    v0 = acc[j][0]; v1 = acc[j][1]; v2 = pc0; v3 = pc1;
                    w0 = acc[j][2]; w1 = acc[j][3]; w2 = pc2; w3 = pc3;
                } else {
                    v0 = pc0; v1 = pc1; v2 = acc[j][0]; v3 = acc[j][1];
                    w0 = pc2; w1 = pc3; w2 = acc[j][2]; w3 = acc[j][3];
                }
                asm volatile("red.global.add.v4.f32 [%0], {%1,%2,%3,%4};"
                             :: "l"(orow0 + nb),
                                "f"(v0), "f"(v1), "f"(v2), "f"(v3) : "memory");
                asm volatile("red.global.add.v4.f32 [%0], {%1,%2,%3,%4};"
                             :: "l"(orow1 + nb),
                                "f"(w0), "f"(w1), "f"(w2), "f"(w3) : "memory");
            }
        }
    }
}

// ---------------------------------------------------------------------------
// Kernel 2: per-column sum / sumsq over the conv output
// grid = 256 blocks x 256 threads; thread (col = tid&63, q = tid>>6)
// ---------------------------------------------------------------------------
__global__ void stats_kernel(const float* __restrict__ out) {
    __shared__ float ssum[256], ssq[256];
    const int tid = threadIdx.x;
    const int col = tid & 63;
    const int q   = tid >> 6;
    const int rowbase = blockIdx.x * 1024;

    float s = 0.f, s2 = 0.f;
    #pragma unroll 4
    for (int i = 0; i < 256; i++) {
        float v = out[(size_t)(rowbase + i * 4 + q) * COUT + col];
        s += v; s2 += v * v;
    }
    ssum[tid] = s; ssq[tid] = s2;
    __syncthreads();
    if (q == 0) {
        s  = ssum[col] + ssum[col + 64] + ssum[col + 128] + ssum[col + 192];
        s2 = ssq[col]  + ssq[col + 64]  + ssq[col + 128]  + ssq[col + 192];
        atomicAdd(&g_sum[col], s);
        atomicAdd(&g_sumsq[col], s2);
    }
}

// ---------------------------------------------------------------------------
// Kernel 3: BN affine + LeakyReLU, in place, float4 vectorized
// ---------------------------------------------------------------------------
__global__ void apply_kernel(float* __restrict__ out,
                             const float* __restrict__ gamma,
                             const float* __restrict__ beta)
{
    __shared__ float sc[COUT], bi[COUT];
    const int tid = threadIdx.x;
    if (tid < COUT) {
        const float inv_n = 1.f / (float)NOUT;
        float mean = g_sum[tid] * inv_n;
        float var  = g_sumsq[tid] * inv_n - mean * mean;
        float s = gamma[tid] * rsqrtf(var + EPS);
        sc[tid] = s;
        bi[tid] = beta[tid] - mean * s;
    }
    __syncthreads();

    const int idx = blockIdx.x * blockDim.x + tid;   // over 4,194,304 float4
    float4* o4 = reinterpret_cast<float4*>(out);
    float4 v = o4[idx];
    const int c = (idx & 15) * 4;
    float y0 = v.x * sc[c + 0] + bi[c + 0];
    float y1 = v.y * sc[c + 1] + bi[c + 1];
    float y2 = v.z * sc[c + 2] + bi[c + 2];
    float y3 = v.w * sc[c + 3] + bi[c + 3];
    v.x = (y0 >= 0.f) ? y0 : SLOPE * y0;
    v.y = (y1 >= 0.f) ? y1 : SLOPE * y1;
    v.z = (y2 >= 0.f) ? y2 : SLOPE * y2;
    v.w = (y3 >= 0.f) ? y3 : SLOPE * y3;
    o4[idx] = v;
}

// ---------------------------------------------------------------------------
// Launch
// inputs (metadata order): feats f32[N_IN*64], W f32[27*64*64], gamma f32[64],
//   beta f32[64], in_map i32[27*M], out_map i32[27*M], num_out i32[1]
// ---------------------------------------------------------------------------
extern "C" void kernel_launch(void* const* d_in, const int* in_sizes, int n_in,
                              void* d_out, int out_size)
{
    const float* feats   = (const float*)d_in[0];
    const float* W       = (const float*)d_in[1];
    const float* gamma   = (const float*)d_in[2];
    const float* beta    = (const float*)d_in[3];
    const int*   in_map  = (const int*)d_in[4];
    const int*   out_map = (const int*)d_in[5];
    float*       out     = (float*)d_out;

    const int n_f4 = (NOUT * COUT) / 4;          // 4,194,304

    zero_kernel<<<n_f4 / 256, 256>>>(reinterpret_cast<float4*>(out));

    dim3 grid(MPAIR / 512, KOFF);                // 256 x 27
    conv_kernel<<<grid, 256>>>(feats, W, in_map, out_map, out);

    stats_kernel<<<256, 256>>>(out);

    apply_kernel<<<n_f4 / 256, 256>>>(out, gamma, beta);
}

// round 3
// speedup vs baseline: 1.0980x; 1.0980x over previous
#include <cuda_runtime.h>
#include <cstdint>

// Problem constants (fixed by the reference)
#define CIN   64
#define COUT  64
#define KOFF  27
#define MPAIR 131072
#define NOUT  262144
#define EPS   1e-5f
#define SLOPE 0.01f

// smem layout for conv kernel (dynamic):
//   [0, 18432)          : Ws  — tf32 W tile, ld = 72 uints per cin row
//   [18432, 18432+34816): buf — 128 staging rows x 68 floats (272B stride)
#define WS_BYTES   (CIN * 72 * 4)
#define BUF_STRIDE 68                    // floats; 272B, multiple of 16B
#define SMEM_BYTES (WS_BYTES + 128 * BUF_STRIDE * 4)

// BN statistics scratch
__device__ float g_sum[COUT];
__device__ float g_sumsq[COUT];

__device__ __forceinline__ uint32_t smem_u32(const void* p) {
    uint32_t a;
    asm("{ .reg .u64 t; cvta.to.shared.u64 t, %1; cvt.u32.u64 %0, t; }"
        : "=r"(a) : "l"(p));
    return a;
}

// ---------------------------------------------------------------------------
// Kernel 0: zero output accumulator + stats scratch
// ---------------------------------------------------------------------------
__global__ void zero_kernel(float4* __restrict__ out4) {
    int idx = blockIdx.x * blockDim.x + threadIdx.x;   // 4,194,304 float4s
    out4[idx] = make_float4(0.f, 0.f, 0.f, 0.f);
    if (blockIdx.x == 0 && threadIdx.x < COUT) {
        g_sum[threadIdx.x]   = 0.f;
        g_sumsq[threadIdx.x] = 0.f;
    }
}

// ---------------------------------------------------------------------------
// Kernel 1: sparse conv. gather -> tf32 mma.sync -> smem stage ->
//           cp.reduce.async.bulk (TMA reduce-add) scatter.
// Block: 256 threads (8 warps). Warp handles 16 pairs/tile, block 128,
// 4 tiles per block. grid = (M/512, K).
// ---------------------------------------------------------------------------
__global__ void __launch_bounds__(256)
conv_kernel(const float* __restrict__ feats,
            const float* __restrict__ W,
            const int*   __restrict__ in_map,
            const int*   __restrict__ out_map,
            float*       __restrict__ out)
{
    extern __shared__ char dynsmem[];
    uint32_t* Ws  = reinterpret_cast<uint32_t*>(dynsmem);
    float*    buf = reinterpret_cast<float*>(dynsmem + WS_BYTES);

    const int k   = blockIdx.y;
    const int tid = threadIdx.x;

    // Load W[k] as tf32 bits, padded ld=72 (72%32==8 -> B-frag LDS
    // addresses (72*a + r) are bank-bijective, conflict-free)
    const float* Wk = W + k * (CIN * COUT);
    for (int i = tid; i < CIN * COUT; i += 256) {
        int kk = i >> 6, n = i & 63;
        uint32_t t;
        asm("cvt.rna.tf32.f32 %0, %1;" : "=r"(t) : "f"(Wk[i]));
        Ws[kk * 72 + n] = t;
    }
    __syncthreads();

    const int warp = tid >> 5;
    const int lane = tid & 31;
    const int r = lane >> 2;   // 0..7  (row within mma group)
    const int a = lane & 3;    // 0..3  (thread-in-group)

    const int* im = in_map  + k * MPAIR;
    const int* om = out_map + k * MPAIR;

    float* wbuf = buf + warp * 16 * BUF_STRIDE;   // 16 private staging rows

    #pragma unroll 1
    for (int t = 0; t < 4; t++) {
        const int base = (blockIdx.x * 4 + t) * 128 + warp * 16;
        const int p0 = base + r;
        const int p1 = p0 + 8;

        const float* arow0 = feats + (size_t)im[p0] * CIN;
        const float* arow1 = feats + (size_t)im[p1] * CIN;

        float acc[8][4];
        #pragma unroll
        for (int j = 0; j < 8; j++)
            #pragma unroll
            for (int q = 0; q < 4; q++) acc[j][q] = 0.f;

        #pragma unroll
        for (int kk = 0; kk < 8; kk++) {
            const int c0 = kk * 8 + a;
            uint32_t a0, a1, a2, a3;
            asm("cvt.rna.tf32.f32 %0, %1;" : "=r"(a0) : "f"(arow0[c0]));
            asm("cvt.rna.tf32.f32 %0, %1;" : "=r"(a1) : "f"(arow1[c0]));
            asm("cvt.rna.tf32.f32 %0, %1;" : "=r"(a2) : "f"(arow0[c0 + 4]));
            asm("cvt.rna.tf32.f32 %0, %1;" : "=r"(a3) : "f"(arow1[c0 + 4]));

            #pragma unroll
            for (int j = 0; j < 8; j++) {
                const uint32_t b0 = Ws[(kk * 8 + a)     * 72 + j * 8 + r];
                const uint32_t b1 = Ws[(kk * 8 + a + 4) * 72 + j * 8 + r];
                asm volatile(
                    "mma.sync.aligned.m16n8k8.row.col.f32.tf32.tf32.f32 "
                    "{%0,%1,%2,%3}, {%4,%5,%6,%7}, {%8,%9}, {%0,%1,%2,%3};"
                    : "+f"(acc[j][0]), "+f"(acc[j][1]),
                      "+f"(acc[j][2]), "+f"(acc[j][3])
                    : "r"(a0), "r"(a1), "r"(a2), "r"(a3),
                      "r"(b0), "r"(b1));
            }
        }

        // --- Epilogue: stage 16 rows in smem, scatter via TMA bulk reduce ---
        // Wait until the async proxy has finished READING our staging rows
        // from the previous tile (the global RMW keeps draining async).
        asm volatile("cp.async.bulk.wait_group.read 0;" ::: "memory");
        __syncwarp();

        // mma D layout: lane(r,a) holds D[r, j*8+2a .. +1] and D[r+8, ...].
        #pragma unroll
        for (int j = 0; j < 8; j++) {
            *reinterpret_cast<float2*>(wbuf + r * BUF_STRIDE + j * 8 + 2 * a)
                = make_float2(acc[j][0], acc[j][1]);
            *reinterpret_cast<float2*>(wbuf + (r + 8) * BUF_STRIDE + j * 8 + 2 * a)
                = make_float2(acc[j][2], acc[j][3]);
        }
        __syncwarp();
        asm volatile("fence.proxy.async.shared::cta;" ::: "memory");

        if (lane < 16) {
            float* dst = out + (size_t)om[base + lane] * COUT;
            uint32_t src = smem_u32(wbuf + lane * BUF_STRIDE);
            asm volatile(
                "cp.reduce.async.bulk.global.shared::cta.bulk_group.add.f32 "
                "[%0], [%1], %2;"
                :: "l"(dst), "r"(src), "r"(256) : "memory");
        }
        asm volatile("cp.async.bulk.commit_group;" ::: "memory");
    }

    // Ensure all reduce WRITES are complete before grid exit (stream order
    // guarantees visibility to the stats kernel).
    asm volatile("cp.async.bulk.wait_group 0;" ::: "memory");
}

// ---------------------------------------------------------------------------
// Kernel 2: per-column sum / sumsq over the conv output
// ---------------------------------------------------------------------------
__global__ void stats_kernel(const float* __restrict__ out) {
    __shared__ float ssum[256], ssq[256];
    const int tid = threadIdx.x;
    const int col = tid & 63;
    const int q   = tid >> 6;
    const int rowbase = blockIdx.x * 1024;

    float s = 0.f, s2 = 0.f;
    #pragma unroll 4
    for (int i = 0; i < 256; i++) {
        float v = out[(size_t)(rowbase + i * 4 + q) * COUT + col];
        s += v; s2 += v * v;
    }
    ssum[tid] = s; ssq[tid] = s2;
    __syncthreads();
    if (q == 0) {
        s  = ssum[col] + ssum[col + 64] + ssum[col + 128] + ssum[col + 192];
        s2 = ssq[col]  + ssq[col + 64]  + ssq[col + 128]  + ssq[col + 192];
        atomicAdd(&g_sum[col], s);
        atomicAdd(&g_sumsq[col], s2);
    }
}

// ---------------------------------------------------------------------------
// Kernel 3: BN affine + LeakyReLU, in place, float4 vectorized
// ---------------------------------------------------------------------------
__global__ void apply_kernel(float* __restrict__ out,
                             const float* __restrict__ gamma,
                             const float* __restrict__ beta)
{
    __shared__ float sc[COUT], bi[COUT];
    const int tid = threadIdx.x;
    if (tid < COUT) {
        const float inv_n = 1.f / (float)NOUT;
        float mean = g_sum[tid] * inv_n;
        float var  = g_sumsq[tid] * inv_n - mean * mean;
        float s = gamma[tid] * rsqrtf(var + EPS);
        sc[tid] = s;
        bi[tid] = beta[tid] - mean * s;
    }
    __syncthreads();

    const int idx = blockIdx.x * blockDim.x + tid;   // over 4,194,304 float4
    float4* o4 = reinterpret_cast<float4*>(out);
    float4 v = o4[idx];
    const int c = (idx & 15) * 4;
    float y0 = v.x * sc[c + 0] + bi[c + 0];
    float y1 = v.y * sc[c + 1] + bi[c + 1];
    float y2 = v.z * sc[c + 2] + bi[c + 2];
    float y3 = v.w * sc[c + 3] + bi[c + 3];
    v.x = (y0 >= 0.f) ? y0 : SLOPE * y0;
    v.y = (y1 >= 0.f) ? y1 : SLOPE * y1;
    v.z = (y2 >= 0.f) ? y2 : SLOPE * y2;
    v.w = (y3 >= 0.f) ? y3 : SLOPE * y3;
    o4[idx] = v;
}

// ---------------------------------------------------------------------------
// Launch
// inputs (metadata order): feats f32[N_IN*64], W f32[27*64*64], gamma f32[64],
//   beta f32[64], in_map i32[27*M], out_map i32[27*M], num_out i32[1]
// ---------------------------------------------------------------------------
extern "C" void kernel_launch(void* const* d_in, const int* in_sizes, int n_in,
                              void* d_out, int out_size)
{
    const float* feats   = (const float*)d_in[0];
    const float* W       = (const float*)d_in[1];
    const float* gamma   = (const float*)d_in[2];
    const float* beta    = (const float*)d_in[3];
    const int*   in_map  = (const int*)d_in[4];
    const int*   out_map = (const int*)d_in[5];
    float*       out     = (float*)d_out;

    const int n_f4 = (NOUT * COUT) / 4;          // 4,194,304

    zero_kernel<<<n_f4 / 256, 256>>>(reinterpret_cast<float4*>(out));

    cudaFuncSetAttribute(conv_kernel,
                         cudaFuncAttributeMaxDynamicSharedMemorySize,
                         SMEM_BYTES);
    dim3 grid(MPAIR / 512, KOFF);                // 256 x 27
    conv_kernel<<<grid, 256, SMEM_BYTES>>>(feats, W, in_map, out_map, out);

    stats_kernel<<<256, 256>>>(out);

    apply_kernel<<<n_f4 / 256, 256>>>(out, gamma, beta);
}